// round 2
// baseline (speedup 1.0000x reference)
#include <cuda_runtime.h>
#include <cuda_bf16.h>
#include <math.h>

// ---------------- problem constants ----------------
#define NMAX 50048            // N = 50000 nodes (padded)
#define FIN  512
#define D1   64               // H1*hid = 8*8
#define H1N  8
#define D2   40               // C (H2=1)

// ---------------- scratch (device globals; no allocation allowed) ----------------
__device__ __align__(16) float g_h1 [NMAX * D1];   // x @ W1
__device__ __align__(16) float g_as1[NMAX * H1N];
__device__ __align__(16) float g_ad1[NMAX * H1N];
__device__ __align__(16) float g_den1[NMAX * H1N]; // sum of exp(e) per (dst, head)
__device__ __align__(16) float g_out1[NMAX * D1];  // sum of exp(e)*h1[src]
__device__ __align__(16) float g_h2 [NMAX * D2];   // relu(norm(out1)+b1) @ W2
__device__ __align__(16) float g_as2[NMAX];
__device__ __align__(16) float g_ad2[NMAX];
__device__ __align__(16) float g_den2[NMAX];
__device__ __align__(16) float g_out2[NMAX * D2];

// ---------------- zero-init (graph replays require re-init every launch) -------
__global__ void k_zero(int Nn) {
    int i0 = blockIdx.x * blockDim.x + threadIdx.x;
    int stride = gridDim.x * blockDim.x;
    for (int i = i0; i < Nn * D1; i += stride) g_out1[i] = 0.f;
    for (int i = i0; i < Nn * D2; i += stride) g_out2[i] = 0.f;
    for (int i = i0; i < Nn * H1N; i += stride) g_den1[i] = 0.f;
    for (int i = i0; i < Nn;       i += stride) g_den2[i] = 0.f;
}

// ---------------- GEMM1: h1 = x @ W1   (M x 512) @ (512 x 64) ------------------
// 64x64 tile, BK=32, 256 threads, 4x4 microtile per thread.
__global__ void k_gemm1(const float* __restrict__ A, const float* __restrict__ B, int M) {
    __shared__ __align__(16) float As[64][33];
    __shared__ __align__(16) float Bs[32][64];
    const int tid = threadIdx.x;
    const int tx = tid & 15, ty = tid >> 4;
    const int row0 = blockIdx.x * 64;
    float acc[4][4];
#pragma unroll
    for (int i = 0; i < 4; i++)
#pragma unroll
        for (int j = 0; j < 4; j++) acc[i][j] = 0.f;

    for (int k0 = 0; k0 < FIN; k0 += 32) {
        // A tile: 64 rows x 32 cols = 512 float4
#pragma unroll
        for (int i = 0; i < 2; i++) {
            int idx = tid + i * 256;
            int r = idx >> 3, c = idx & 7;
            float4 v = make_float4(0.f, 0.f, 0.f, 0.f);
            int gr = row0 + r;
            if (gr < M) v = *(const float4*)(A + (size_t)gr * FIN + k0 + c * 4);
            As[r][c * 4 + 0] = v.x; As[r][c * 4 + 1] = v.y;
            As[r][c * 4 + 2] = v.z; As[r][c * 4 + 3] = v.w;
        }
        // B tile: 32 rows x 64 cols = 512 float4
#pragma unroll
        for (int i = 0; i < 2; i++) {
            int idx = tid + i * 256;
            int r = idx >> 4, c = idx & 15;
            float4 v = *(const float4*)(B + (size_t)(k0 + r) * D1 + c * 4);
            *(float4*)&Bs[r][c * 4] = v;
        }
        __syncthreads();
#pragma unroll
        for (int kk = 0; kk < 32; kk++) {
            float a[4];
#pragma unroll
            for (int i = 0; i < 4; i++) a[i] = As[ty * 4 + i][kk];
            float4 bv = *(float4*)&Bs[kk][tx * 4];
            float b[4] = {bv.x, bv.y, bv.z, bv.w};
#pragma unroll
            for (int i = 0; i < 4; i++)
#pragma unroll
                for (int j = 0; j < 4; j++) acc[i][j] += a[i] * b[j];
        }
        __syncthreads();
    }
#pragma unroll
    for (int i = 0; i < 4; i++) {
        int gr = row0 + ty * 4 + i;
        if (gr < M) {
#pragma unroll
            for (int j = 0; j < 4; j++)
                g_h1[(size_t)gr * D1 + tx * 4 + j] = acc[i][j];
        }
    }
}

// ---------------- attention coefficients, layer 1 ------------------------------
__global__ void k_att1(const float* __restrict__ asrc, const float* __restrict__ adst, int Nn) {
    int idx = blockIdx.x * blockDim.x + threadIdx.x;
    if (idx >= Nn * H1N) return;
    int n = idx >> 3, h = idx & 7;
    const float* hp = g_h1 + (size_t)n * D1 + h * 8;
    float s = 0.f, d = 0.f;
#pragma unroll
    for (int c = 0; c < 8; c++) {
        float v = hp[c];
        s += v * __ldg(asrc + h * 8 + c);
        d += v * __ldg(adst + h * 8 + c);
    }
    g_as1[idx] = s;
    g_ad1[idx] = d;
}

// ---------------- edge pass, layer 1 (warp per edge) ---------------------------
// Accumulates den1[dst,h] += exp(e) and out1[dst,f] += exp(e)*h1[src,f].
__global__ void k_edge1(const int* __restrict__ ei, int E, int Nn) {
    int w = (blockIdx.x * blockDim.x + threadIdx.x) >> 5;
    int lane = threadIdx.x & 31;
    if (w >= E + Nn) return;
    int src, dst;
    if (w < E) { src = ei[w]; dst = ei[E + w]; }
    else       { src = dst = w - E; }

    float ex = 0.f;
    if (lane < 8) {
        float e = g_as1[src * H1N + lane] + g_ad1[dst * H1N + lane];
        e = (e >= 0.f) ? e : 0.2f * e;           // leaky relu, slope 0.2
        ex = expf(e);
        atomicAdd(&g_den1[dst * H1N + lane], ex);
    }
    float e0 = __shfl_sync(0xffffffffu, ex, lane >> 3);
    float e1 = __shfl_sync(0xffffffffu, ex, (lane >> 3) + 4);
    const float* hs = g_h1 + (size_t)src * D1;
    float* op = g_out1 + (size_t)dst * D1;
    atomicAdd(op + lane,      e0 * hs[lane]);
    atomicAdd(op + lane + 32, e1 * hs[lane + 32]);
}

// ---------------- GEMM2: h2 = relu(out1/den1 + b1) @ W2  (M x 64) @ (64 x 40) --
__global__ void k_gemm2(const float* __restrict__ W2, const float* __restrict__ b1v, int M) {
    __shared__ __align__(16) float As[64][65];
    __shared__ __align__(16) float Bs[64][D2];
    const int tid = threadIdx.x;
    const int row0 = blockIdx.x * 64;

    for (int idx = tid; idx < 64 * D2; idx += 256)
        Bs[idx / D2][idx % D2] = W2[idx];

#pragma unroll
    for (int i = 0; i < 4; i++) {
        int idx = tid + i * 256;          // 1024 float4 over 64x64
        int r = idx >> 4, c = idx & 15;
        int gr = row0 + r;
        float4 v = make_float4(0.f, 0.f, 0.f, 0.f);
        if (gr < M) {
            v = *(const float4*)(g_out1 + (size_t)gr * D1 + c * 4);
            float inv = 1.f / (g_den1[gr * H1N + (c >> 1)] + 1e-16f); // 4 consec elems share a head
            v.x = fmaxf(v.x * inv + __ldg(b1v + c * 4 + 0), 0.f);
            v.y = fmaxf(v.y * inv + __ldg(b1v + c * 4 + 1), 0.f);
            v.z = fmaxf(v.z * inv + __ldg(b1v + c * 4 + 2), 0.f);
            v.w = fmaxf(v.w * inv + __ldg(b1v + c * 4 + 3), 0.f);
        }
        As[r][c * 4 + 0] = v.x; As[r][c * 4 + 1] = v.y;
        As[r][c * 4 + 2] = v.z; As[r][c * 4 + 3] = v.w;
    }
    __syncthreads();

    int row = tid & 63;
    int cg  = tid >> 6;                   // 4 col-groups of 10
    float acc[10];
#pragma unroll
    for (int j = 0; j < 10; j++) acc[j] = 0.f;
#pragma unroll
    for (int k = 0; k < 64; k++) {
        float a = As[row][k];
#pragma unroll
        for (int j = 0; j < 10; j++) acc[j] += a * Bs[k][cg * 10 + j];
    }
    int gr = row0 + row;
    if (gr < M) {
#pragma unroll
        for (int j = 0; j < 10; j++)
            g_h2[(size_t)gr * D2 + cg * 10 + j] = acc[j];
    }
}

// ---------------- attention coefficients, layer 2 ------------------------------
__global__ void k_att2(const float* __restrict__ s2, const float* __restrict__ d2, int Nn) {
    int n = blockIdx.x * blockDim.x + threadIdx.x;
    if (n >= Nn) return;
    const float* hp = g_h2 + (size_t)n * D2;
    float s = 0.f, d = 0.f;
#pragma unroll
    for (int j = 0; j < D2; j++) {
        float v = hp[j];
        s += v * __ldg(s2 + j);
        d += v * __ldg(d2 + j);
    }
    g_as2[n] = s;
    g_ad2[n] = d;
}

// ---------------- edge pass, layer 2 (warp per edge) ---------------------------
__global__ void k_edge2(const int* __restrict__ ei, int E, int Nn) {
    int w = (blockIdx.x * blockDim.x + threadIdx.x) >> 5;
    int lane = threadIdx.x & 31;
    if (w >= E + Nn) return;
    int src, dst;
    if (w < E) { src = ei[w]; dst = ei[E + w]; }
    else       { src = dst = w - E; }

    float ex = 0.f;
    if (lane == 0) {
        float e = g_as2[src] + g_ad2[dst];
        e = (e >= 0.f) ? e : 0.2f * e;
        ex = expf(e);
        atomicAdd(&g_den2[dst], ex);
    }
    ex = __shfl_sync(0xffffffffu, ex, 0);
    const float* hs = g_h2 + (size_t)src * D2;
    float* op = g_out2 + (size_t)dst * D2;
    atomicAdd(op + lane, ex * hs[lane]);
    if (lane < 8) atomicAdd(op + 32 + lane, ex * hs[32 + lane]);
}

// ---------------- final: normalize + bias + log_softmax (warp per node) --------
__global__ void k_lsm(const float* __restrict__ b2, float* __restrict__ out, int Nn) {
    int w = (blockIdx.x * blockDim.x + threadIdx.x) >> 5;
    int lane = threadIdx.x & 31;
    if (w >= Nn) return;
    float inv = 1.f / (g_den2[w] + 1e-16f);
    const float* op = g_out2 + (size_t)w * D2;
    float v0 = op[lane] * inv + __ldg(b2 + lane);
    float v1 = (lane < 8) ? (op[32 + lane] * inv + __ldg(b2 + 32 + lane)) : -3.4e38f;
    float m = fmaxf(v0, v1);
#pragma unroll
    for (int off = 16; off; off >>= 1) m = fmaxf(m, __shfl_xor_sync(0xffffffffu, m, off));
    float s = expf(v0 - m) + ((lane < 8) ? expf(v1 - m) : 0.f);
#pragma unroll
    for (int off = 16; off; off >>= 1) s += __shfl_xor_sync(0xffffffffu, s, off);
    float l = m + logf(s);
    out[(size_t)w * D2 + lane] = v0 - l;
    if (lane < 8) out[(size_t)w * D2 + 32 + lane] = v1 - l;
}

// ---------------- launch --------------------------------------------------------
extern "C" void kernel_launch(void* const* d_in, const int* in_sizes, int n_in,
                              void* d_out, int out_size) {
    const float* x   = (const float*)d_in[0];
    const int*   ei  = (const int*)d_in[1];       // int32! (JAX x64 disabled)
    const float* W1  = (const float*)d_in[2];
    const float* as1 = (const float*)d_in[3];
    const float* ad1 = (const float*)d_in[4];
    const float* b1  = (const float*)d_in[5];
    const float* W2  = (const float*)d_in[6];
    const float* as2 = (const float*)d_in[7];
    const float* ad2 = (const float*)d_in[8];
    const float* b2  = (const float*)d_in[9];

    int Nn = in_sizes[0] / FIN;      // 50000
    int E  = in_sizes[1] / 2;        // 1600000
    int EP = E + Nn;                 // edges + self loops

    k_zero <<<2048, 256>>>(Nn);
    k_gemm1<<<(Nn + 63) / 64, 256>>>(x, W1, Nn);
    k_att1 <<<(Nn * H1N + 255) / 256, 256>>>(as1, ad1, Nn);
    k_edge1<<<(EP + 7) / 8, 256>>>(ei, E, Nn);
    k_gemm2<<<(Nn + 63) / 64, 256>>>(W2, b1, Nn);
    k_att2 <<<(Nn + 255) / 256, 256>>>(as2, ad2, Nn);
    k_edge2<<<(EP + 7) / 8, 256>>>(ei, E, Nn);
    k_lsm  <<<(Nn + 7) / 8, 256>>>(b2, (float*)d_out, Nn);
}

// round 3
// speedup vs baseline: 1.5269x; 1.5269x over previous
#include <cuda_runtime.h>
#include <cuda_bf16.h>
#include <math.h>

// ---------------- problem constants ----------------
#define NMAX 50048            // N = 50000 nodes (padded)
#define FIN  512
#define D1   64               // H1*hid = 8*8
#define H1N  8
#define D2   40               // C (H2=1)

// ---------------- scratch (device globals; no allocation allowed) ----------------
__device__ __align__(16) float g_h1 [NMAX * D1];   // x @ W1
__device__ __align__(16) float g_as1[NMAX * H1N];
__device__ __align__(16) float g_ad1[NMAX * H1N];
__device__ __align__(16) float g_den1[NMAX * H1N]; // sum of exp(e) per (dst, head)
__device__ __align__(16) float g_out1[NMAX * D1];  // sum of exp(e)*h1[src]
__device__ __align__(16) float g_h2 [NMAX * D2];   // relu(norm(out1)+b1) @ W2
__device__ __align__(16) float g_as2[NMAX];
__device__ __align__(16) float g_ad2[NMAX];
__device__ __align__(16) float g_den2[NMAX];
__device__ __align__(16) float g_out2[NMAX * D2];

__device__ __forceinline__ void red_v4(float* p, float4 v) {
    asm volatile("red.global.add.v4.f32 [%0], {%1,%2,%3,%4};"
                 :: "l"(p), "f"(v.x), "f"(v.y), "f"(v.z), "f"(v.w) : "memory");
}

// ---------------- zero-init (graph replays require re-init every launch) -------
__global__ void k_zero(int Nn) {
    int i0 = blockIdx.x * blockDim.x + threadIdx.x;
    int stride = gridDim.x * blockDim.x;
    float4 z = make_float4(0.f, 0.f, 0.f, 0.f);
    for (int i = i0; i < Nn * D1 / 4; i += stride) ((float4*)g_out1)[i] = z;
    for (int i = i0; i < Nn * D2 / 4; i += stride) ((float4*)g_out2)[i] = z;
    for (int i = i0; i < Nn * H1N / 4; i += stride) ((float4*)g_den1)[i] = z;
    for (int i = i0; i < Nn;           i += stride) g_den2[i] = 0.f;
}

// ---------------- GEMM1: h1 = x @ W1   (M x 512) @ (512 x 64) ------------------
__global__ void k_gemm1(const float* __restrict__ A, const float* __restrict__ B, int M) {
    __shared__ __align__(16) float As[64][33];
    __shared__ __align__(16) float Bs[32][64];
    const int tid = threadIdx.x;
    const int tx = tid & 15, ty = tid >> 4;
    const int row0 = blockIdx.x * 64;
    float acc[4][4];
#pragma unroll
    for (int i = 0; i < 4; i++)
#pragma unroll
        for (int j = 0; j < 4; j++) acc[i][j] = 0.f;

    for (int k0 = 0; k0 < FIN; k0 += 32) {
#pragma unroll
        for (int i = 0; i < 2; i++) {
            int idx = tid + i * 256;
            int r = idx >> 3, c = idx & 7;
            float4 v = make_float4(0.f, 0.f, 0.f, 0.f);
            int gr = row0 + r;
            if (gr < M) v = *(const float4*)(A + (size_t)gr * FIN + k0 + c * 4);
            As[r][c * 4 + 0] = v.x; As[r][c * 4 + 1] = v.y;
            As[r][c * 4 + 2] = v.z; As[r][c * 4 + 3] = v.w;
        }
#pragma unroll
        for (int i = 0; i < 2; i++) {
            int idx = tid + i * 256;
            int r = idx >> 4, c = idx & 15;
            float4 v = *(const float4*)(B + (size_t)(k0 + r) * D1 + c * 4);
            *(float4*)&Bs[r][c * 4] = v;
        }
        __syncthreads();
#pragma unroll
        for (int kk = 0; kk < 32; kk++) {
            float a[4];
#pragma unroll
            for (int i = 0; i < 4; i++) a[i] = As[ty * 4 + i][kk];
            float4 bv = *(float4*)&Bs[kk][tx * 4];
            float b[4] = {bv.x, bv.y, bv.z, bv.w};
#pragma unroll
            for (int i = 0; i < 4; i++)
#pragma unroll
                for (int j = 0; j < 4; j++) acc[i][j] += a[i] * b[j];
        }
        __syncthreads();
    }
#pragma unroll
    for (int i = 0; i < 4; i++) {
        int gr = row0 + ty * 4 + i;
        if (gr < M) {
#pragma unroll
            for (int j = 0; j < 4; j++)
                g_h1[(size_t)gr * D1 + tx * 4 + j] = acc[i][j];
        }
    }
}

// ---------------- attention coefficients, layer 1 ------------------------------
__global__ void k_att1(const float* __restrict__ asrc, const float* __restrict__ adst, int Nn) {
    int idx = blockIdx.x * blockDim.x + threadIdx.x;
    if (idx >= Nn * H1N) return;
    int n = idx >> 3, h = idx & 7;
    const float* hp = g_h1 + (size_t)n * D1 + h * 8;
    float s = 0.f, d = 0.f;
#pragma unroll
    for (int c = 0; c < 8; c++) {
        float v = hp[c];
        s += v * __ldg(asrc + h * 8 + c);
        d += v * __ldg(adst + h * 8 + c);
    }
    g_as1[idx] = s;
    g_ad1[idx] = d;
}

// ---------------- edge pass, layer 1: half-warp per edge, v4 reductions --------
// den1[dst,h] += exp(e_h);  out1[dst, :] += exp(e_h) * h1[src, :]
__global__ void k_edge1(const int* __restrict__ ei, int E, int EP) {
    int warp = (blockIdx.x * blockDim.x + threadIdx.x) >> 5;
    int lane = threadIdx.x & 31;
    int half = lane >> 4;            // which edge of the pair
    int lh   = lane & 15;            // lane within half-warp
    int e = warp * 2 + half;
    bool active = (e < EP);
    int src = 0, dst = 0;
    if (active) {
        if (e < E) { src = __ldg(ei + e); dst = __ldg(ei + E + e); }
        else       { src = dst = e - E; }
    }

    float ex = 0.f;
    if (lh < 8) {
        float v = g_as1[src * H1N + lh] + g_ad1[dst * H1N + lh];
        v = (v >= 0.f) ? v : 0.2f * v;               // leaky relu
        ex = __expf(v);
        if (active) atomicAdd(&g_den1[dst * H1N + lh], ex);
    }
    // float4 block lh covers features 4*lh..4*lh+3 -> head lh>>1
    float exh = __shfl_sync(0xffffffffu, ex, (half << 4) + (lh >> 1));
    if (active) {
        float4 hv = *(const float4*)(g_h1 + (size_t)src * D1 + lh * 4);
        red_v4(g_out1 + (size_t)dst * D1 + lh * 4,
               make_float4(hv.x * exh, hv.y * exh, hv.z * exh, hv.w * exh));
    }
}

// ---------------- GEMM2: h2 = relu(out1/den1 + b1) @ W2  (M x 64) @ (64 x 40) --
__global__ void k_gemm2(const float* __restrict__ W2, const float* __restrict__ b1v, int M) {
    __shared__ __align__(16) float As[64][65];
    __shared__ __align__(16) float Bs[64][D2];
    const int tid = threadIdx.x;
    const int row0 = blockIdx.x * 64;

    for (int idx = tid; idx < 64 * D2; idx += 256)
        Bs[idx / D2][idx % D2] = W2[idx];

#pragma unroll
    for (int i = 0; i < 4; i++) {
        int idx = tid + i * 256;
        int r = idx >> 4, c = idx & 15;
        int gr = row0 + r;
        float4 v = make_float4(0.f, 0.f, 0.f, 0.f);
        if (gr < M) {
            v = *(const float4*)(g_out1 + (size_t)gr * D1 + c * 4);
            float inv = 1.f / (g_den1[gr * H1N + (c >> 1)] + 1e-16f);
            v.x = fmaxf(v.x * inv + __ldg(b1v + c * 4 + 0), 0.f);
            v.y = fmaxf(v.y * inv + __ldg(b1v + c * 4 + 1), 0.f);
            v.z = fmaxf(v.z * inv + __ldg(b1v + c * 4 + 2), 0.f);
            v.w = fmaxf(v.w * inv + __ldg(b1v + c * 4 + 3), 0.f);
        }
        As[r][c * 4 + 0] = v.x; As[r][c * 4 + 1] = v.y;
        As[r][c * 4 + 2] = v.z; As[r][c * 4 + 3] = v.w;
    }
    __syncthreads();

    int row = tid & 63;
    int cg  = tid >> 6;
    float acc[10];
#pragma unroll
    for (int j = 0; j < 10; j++) acc[j] = 0.f;
#pragma unroll
    for (int k = 0; k < 64; k++) {
        float a = As[row][k];
#pragma unroll
        for (int j = 0; j < 10; j++) acc[j] += a * Bs[k][cg * 10 + j];
    }
    int gr = row0 + row;
    if (gr < M) {
#pragma unroll
        for (int j = 0; j < 10; j++)
            g_h2[(size_t)gr * D2 + cg * 10 + j] = acc[j];
    }
}

// ---------------- attention coefficients, layer 2 ------------------------------
__global__ void k_att2(const float* __restrict__ s2, const float* __restrict__ d2, int Nn) {
    int n = blockIdx.x * blockDim.x + threadIdx.x;
    if (n >= Nn) return;
    const float* hp = g_h2 + (size_t)n * D2;
    float s = 0.f, d = 0.f;
#pragma unroll
    for (int j = 0; j < D2; j++) {
        float v = hp[j];
        s += v * __ldg(s2 + j);
        d += v * __ldg(d2 + j);
    }
    g_as2[n] = s;
    g_ad2[n] = d;
}

// ---------------- edge pass, layer 2: half-warp per edge, v4 reductions --------
__global__ void k_edge2(const int* __restrict__ ei, int E, int EP) {
    int warp = (blockIdx.x * blockDim.x + threadIdx.x) >> 5;
    int lane = threadIdx.x & 31;
    int half = lane >> 4;
    int lh   = lane & 15;
    int e = warp * 2 + half;
    bool active = (e < EP);
    int src = 0, dst = 0;
    if (active) {
        if (e < E) { src = __ldg(ei + e); dst = __ldg(ei + E + e); }
        else       { src = dst = e - E; }
    }

    float v = g_as2[src] + g_ad2[dst];
    v = (v >= 0.f) ? v : 0.2f * v;
    float ex = __expf(v);
    if (active && lh == 0) atomicAdd(&g_den2[dst], ex);
    if (active && lh < 10) {
        float4 hv = *(const float4*)(g_h2 + (size_t)src * D2 + lh * 4);
        red_v4(g_out2 + (size_t)dst * D2 + lh * 4,
               make_float4(hv.x * ex, hv.y * ex, hv.z * ex, hv.w * ex));
    }
}

// ---------------- final: normalize + bias + log_softmax (warp per node) --------
__global__ void k_lsm(const float* __restrict__ b2, float* __restrict__ out, int Nn) {
    int w = (blockIdx.x * blockDim.x + threadIdx.x) >> 5;
    int lane = threadIdx.x & 31;
    if (w >= Nn) return;
    float inv = 1.f / (g_den2[w] + 1e-16f);
    const float* op = g_out2 + (size_t)w * D2;
    float v0 = op[lane] * inv + __ldg(b2 + lane);
    float v1 = (lane < 8) ? (op[32 + lane] * inv + __ldg(b2 + 32 + lane)) : -3.4e38f;
    float m = fmaxf(v0, v1);
#pragma unroll
    for (int off = 16; off; off >>= 1) m = fmaxf(m, __shfl_xor_sync(0xffffffffu, m, off));
    float s = expf(v0 - m) + ((lane < 8) ? expf(v1 - m) : 0.f);
#pragma unroll
    for (int off = 16; off; off >>= 1) s += __shfl_xor_sync(0xffffffffu, s, off);
    float l = m + logf(s);
    out[(size_t)w * D2 + lane] = v0 - l;
    if (lane < 8) out[(size_t)w * D2 + 32 + lane] = v1 - l;
}

// ---------------- launch --------------------------------------------------------
extern "C" void kernel_launch(void* const* d_in, const int* in_sizes, int n_in,
                              void* d_out, int out_size) {
    const float* x   = (const float*)d_in[0];
    const int*   ei  = (const int*)d_in[1];       // int32 (JAX x64 disabled)
    const float* W1  = (const float*)d_in[2];
    const float* as1 = (const float*)d_in[3];
    const float* ad1 = (const float*)d_in[4];
    const float* b1  = (const float*)d_in[5];
    const float* W2  = (const float*)d_in[6];
    const float* as2 = (const float*)d_in[7];
    const float* ad2 = (const float*)d_in[8];
    const float* b2  = (const float*)d_in[9];

    int Nn = in_sizes[0] / FIN;      // 50000
    int E  = in_sizes[1] / 2;        // 1600000
    int EP = E + Nn;                 // edges + self loops
    int ewarps  = (EP + 1) / 2;      // 2 edges per warp
    int eblocks = (ewarps + 7) / 8;  // 8 warps per block

    k_zero <<<1024, 256>>>(Nn);
    k_gemm1<<<(Nn + 63) / 64, 256>>>(x, W1, Nn);
    k_att1 <<<(Nn * H1N + 255) / 256, 256>>>(as1, ad1, Nn);
    k_edge1<<<eblocks, 256>>>(ei, E, EP);
    k_gemm2<<<(Nn + 63) / 64, 256>>>(W2, b1, Nn);
    k_att2 <<<(Nn + 255) / 256, 256>>>(as2, ad2, Nn);
    k_edge2<<<eblocks, 256>>>(ei, E, EP);
    k_lsm  <<<(Nn + 7) / 8, 256>>>(b2, (float*)d_out, Nn);
}

// round 4
// speedup vs baseline: 1.5805x; 1.0351x over previous
#include <cuda_runtime.h>
#include <cuda_bf16.h>
#include <math.h>

// ---------------- problem constants ----------------
#define NMAX 50048            // N = 50000 nodes (padded)
#define FIN  512
#define D1   64               // H1*hid = 8*8
#define H1N  8
#define D2   40               // C (H2=1)
#define S1   72               // padded accumulator stride: 64 features + 8 den

// ---------------- scratch (device globals; no allocation allowed) ----------------
__device__ __align__(16) float g_h1 [NMAX * D1];   // x @ W1
__device__ __align__(16) float g_as1[NMAX * H1N];
__device__ __align__(16) float g_ad1[NMAX * H1N];
__device__ __align__(16) float g_acc1[NMAX * S1];  // [feat(64) | den(8)] per node
__device__ __align__(16) float g_h2 [NMAX * D2];   // relu(norm+b1) @ W2
__device__ __align__(16) float g_as2[NMAX];
__device__ __align__(16) float g_ad2[NMAX];
__device__ __align__(16) float g_den2[NMAX];
__device__ __align__(16) float g_out2[NMAX * D2];

__device__ __forceinline__ void red_v4(float* p, float4 v) {
    asm volatile("red.global.add.v4.f32 [%0], {%1,%2,%3,%4};"
                 :: "l"(p), "f"(v.x), "f"(v.y), "f"(v.z), "f"(v.w) : "memory");
}
__device__ __forceinline__ unsigned tf32_of(float x) {
    unsigned r;
    asm("cvt.rna.tf32.f32 %0, %1;" : "=r"(r) : "f"(x));
    return r;
}

// ---------------- zero-init (graph replays require re-init every launch) -------
__global__ void k_zero(int Nn) {
    int i0 = blockIdx.x * blockDim.x + threadIdx.x;
    int stride = gridDim.x * blockDim.x;
    float4 z = make_float4(0.f, 0.f, 0.f, 0.f);
    for (int i = i0; i < Nn * S1 / 4; i += stride) ((float4*)g_acc1)[i] = z;
    for (int i = i0; i < Nn * D2 / 4; i += stride) ((float4*)g_out2)[i] = z;
    for (int i = i0; i < Nn;          i += stride) g_den2[i] = 0.f;
}

// ---------------- GEMM1 (tf32 MMA): h1 = x @ W1   (M x 512) @ (512 x 64) -------
// Block: 256 thr (8 warps), tile M=128 N=64, BK=32. Warp w: rows 16w..16w+15, all N.
// Smem layout [row][kw(8)][kb(4)], row stride 36 floats: fragment loads are LDS.128.
__global__ void k_gemm1(const float* __restrict__ A, const float* __restrict__ B, int M) {
    __shared__ __align__(16) float As[128 * 36];
    __shared__ __align__(16) float Bs[64 * 36];
    const int tid  = threadIdx.x;
    const int warp = tid >> 5, lane = tid & 31;
    const int row0 = blockIdx.x * 128;
    const int lr = lane >> 2, lc = lane & 3;     // fragment row/col within tile

    float acc[8][4];
#pragma unroll
    for (int nt = 0; nt < 8; nt++)
#pragma unroll
        for (int j = 0; j < 4; j++) acc[nt][j] = 0.f;

    for (int k0 = 0; k0 < FIN; k0 += 32) {
        // A tile: 128x32 = 1024 float4 loads, 4 per thread, tf32-round at store
#pragma unroll
        for (int i = 0; i < 4; i++) {
            int idx = tid + i * 256;
            int r = idx >> 3, c4 = idx & 7;
            float4 v = make_float4(0.f, 0.f, 0.f, 0.f);
            int gr = row0 + r;
            if (gr < M) v = *(const float4*)(A + (size_t)gr * FIN + k0 + c4 * 4);
            int c = c4 * 4;
            As[r * 36 + ((c + 0) & 7) * 4 + ((c + 0) >> 3)] = __uint_as_float(tf32_of(v.x));
            As[r * 36 + ((c + 1) & 7) * 4 + ((c + 1) >> 3)] = __uint_as_float(tf32_of(v.y));
            As[r * 36 + ((c + 2) & 7) * 4 + ((c + 2) >> 3)] = __uint_as_float(tf32_of(v.z));
            As[r * 36 + ((c + 3) & 7) * 4 + ((c + 3) >> 3)] = __uint_as_float(tf32_of(v.w));
        }
        // B tile: 32x64 = 512 float4 loads, 2 per thread
#pragma unroll
        for (int i = 0; i < 2; i++) {
            int idx = tid + i * 256;
            int k = idx >> 4, c4 = idx & 15;
            float4 v = *(const float4*)(B + (size_t)(k0 + k) * D1 + c4 * 4);
            int kk = ((k & 7) << 2) + (k >> 3);
            Bs[(c4 * 4 + 0) * 36 + kk] = __uint_as_float(tf32_of(v.x));
            Bs[(c4 * 4 + 1) * 36 + kk] = __uint_as_float(tf32_of(v.y));
            Bs[(c4 * 4 + 2) * 36 + kk] = __uint_as_float(tf32_of(v.z));
            Bs[(c4 * 4 + 3) * 36 + kk] = __uint_as_float(tf32_of(v.w));
        }
        __syncthreads();

        // A fragments: 4 LDS.128 cover all 4 k-steps x 4 a-regs
        const float* ab = As + (warp * 16 + lr) * 36;
        float4 a00 = *(const float4*)(ab +       lc * 4);        // row lr,   cols lc   (kb 0..3)
        float4 a10 = *(const float4*)(ab + 8*36 + lc * 4);       // row lr+8, cols lc
        float4 a01 = *(const float4*)(ab +       (lc + 4) * 4);  // row lr,   cols lc+4
        float4 a11 = *(const float4*)(ab + 8*36 + (lc + 4) * 4); // row lr+8, cols lc+4
        const unsigned* a00u = (const unsigned*)&a00;
        const unsigned* a10u = (const unsigned*)&a10;
        const unsigned* a01u = (const unsigned*)&a01;
        const unsigned* a11u = (const unsigned*)&a11;

#pragma unroll
        for (int nt = 0; nt < 8; nt++) {
            const float* bb = Bs + (nt * 8 + lr) * 36;
            float4 b0v = *(const float4*)(bb + lc * 4);          // k rows lc,   kb 0..3
            float4 b1v = *(const float4*)(bb + (lc + 4) * 4);    // k rows lc+4, kb 0..3
            const unsigned* b0u = (const unsigned*)&b0v;
            const unsigned* b1u = (const unsigned*)&b1v;
#pragma unroll
            for (int ks = 0; ks < 4; ks++) {
                asm volatile(
                    "mma.sync.aligned.m16n8k8.row.col.f32.tf32.tf32.f32 "
                    "{%0,%1,%2,%3}, {%4,%5,%6,%7}, {%8,%9}, {%0,%1,%2,%3};"
                    : "+f"(acc[nt][0]), "+f"(acc[nt][1]), "+f"(acc[nt][2]), "+f"(acc[nt][3])
                    : "r"(a00u[ks]), "r"(a10u[ks]), "r"(a01u[ks]), "r"(a11u[ks]),
                      "r"(b0u[ks]), "r"(b1u[ks]));
            }
        }
        __syncthreads();
    }

    // store C: c0,c1 -> (row, 2*lc + nt*8), c2,c3 -> (row+8, ...)
    int gr = row0 + warp * 16 + lr;
#pragma unroll
    for (int nt = 0; nt < 8; nt++) {
        int col = nt * 8 + lc * 2;
        if (gr < M)     *(float2*)(g_h1 + (size_t)gr * D1 + col)       = make_float2(acc[nt][0], acc[nt][1]);
        if (gr + 8 < M) *(float2*)(g_h1 + (size_t)(gr + 8) * D1 + col) = make_float2(acc[nt][2], acc[nt][3]);
    }
}

// ---------------- attention coefficients, layer 1 ------------------------------
__global__ void k_att1(const float* __restrict__ asrc, const float* __restrict__ adst, int Nn) {
    int idx = blockIdx.x * blockDim.x + threadIdx.x;
    if (idx >= Nn * H1N) return;
    int n = idx >> 3, h = idx & 7;
    const float* hp = g_h1 + (size_t)n * D1 + h * 8;
    float s = 0.f, d = 0.f;
#pragma unroll
    for (int c = 0; c < 8; c++) {
        float v = hp[c];
        s += v * __ldg(asrc + h * 8 + c);
        d += v * __ldg(adst + h * 8 + c);
    }
    g_as1[idx] = s;
    g_ad1[idx] = d;
}

// ---------------- edge pass, layer 1: half-warp per edge, all-v4 reductions ----
// acc1[dst, 0:64] += exp(e_h)*h1[src, :];  acc1[dst, 64+h] += exp(e_h)
__global__ void k_edge1(const int* __restrict__ ei, int E, int EP) {
    int warp = (blockIdx.x * blockDim.x + threadIdx.x) >> 5;
    int lane = threadIdx.x & 31;
    int half = lane >> 4;            // which edge of the pair
    int lh   = lane & 15;            // lane within half-warp
    int e = warp * 2 + half;
    bool active = (e < EP);
    int src = 0, dst = 0;
    if (active) {
        if (e < E) { src = __ldg(ei + e); dst = __ldg(ei + E + e); }
        else       { src = dst = e - E; }
    }

    float ex = 0.f;
    if (lh < 8) {
        float v = g_as1[src * H1N + lh] + g_ad1[dst * H1N + lh];
        v = (v >= 0.f) ? v : 0.2f * v;               // leaky relu
        ex = __expf(v);
    }
    int base = half << 4;
    // feature red: lane lh covers features 4lh..4lh+3 -> head lh>>1
    float exh = __shfl_sync(0xffffffffu, ex, base + (lh >> 1));
    // den red: lanes lh==0 -> ex[0..3], lh==1 -> ex[4..7]
    float d0 = __shfl_sync(0xffffffffu, ex, base + ((lh * 4 + 0) & 15));
    float d1 = __shfl_sync(0xffffffffu, ex, base + ((lh * 4 + 1) & 15));
    float d2 = __shfl_sync(0xffffffffu, ex, base + ((lh * 4 + 2) & 15));
    float d3 = __shfl_sync(0xffffffffu, ex, base + ((lh * 4 + 3) & 15));
    if (active) {
        float4 hv = *(const float4*)(g_h1 + (size_t)src * D1 + lh * 4);
        red_v4(g_acc1 + (size_t)dst * S1 + lh * 4,
               make_float4(hv.x * exh, hv.y * exh, hv.z * exh, hv.w * exh));
        if (lh < 2)
            red_v4(g_acc1 + (size_t)dst * S1 + 64 + lh * 4, make_float4(d0, d1, d2, d3));
    }
}

// ---------------- GEMM2: h2 = relu(acc1/den + b1) @ W2  (M x 64) @ (64 x 40) ---
__global__ void k_gemm2(const float* __restrict__ W2, const float* __restrict__ b1v, int M) {
    __shared__ __align__(16) float As[64][65];
    __shared__ __align__(16) float Bs[64][D2];
    const int tid = threadIdx.x;
    const int row0 = blockIdx.x * 64;

    for (int idx = tid; idx < 64 * D2; idx += 256)
        Bs[idx / D2][idx % D2] = W2[idx];

#pragma unroll
    for (int i = 0; i < 4; i++) {
        int idx = tid + i * 256;
        int r = idx >> 4, c = idx & 15;
        int gr = row0 + r;
        float4 v = make_float4(0.f, 0.f, 0.f, 0.f);
        if (gr < M) {
            v = *(const float4*)(g_acc1 + (size_t)gr * S1 + c * 4);
            float inv = 1.f / (g_acc1[(size_t)gr * S1 + 64 + (c >> 1)] + 1e-16f);
            v.x = fmaxf(v.x * inv + __ldg(b1v + c * 4 + 0), 0.f);
            v.y = fmaxf(v.y * inv + __ldg(b1v + c * 4 + 1), 0.f);
            v.z = fmaxf(v.z * inv + __ldg(b1v + c * 4 + 2), 0.f);
            v.w = fmaxf(v.w * inv + __ldg(b1v + c * 4 + 3), 0.f);
        }
        As[r][c * 4 + 0] = v.x; As[r][c * 4 + 1] = v.y;
        As[r][c * 4 + 2] = v.z; As[r][c * 4 + 3] = v.w;
    }
    __syncthreads();

    int row = tid & 63;
    int cg  = tid >> 6;
    float acc[10];
#pragma unroll
    for (int j = 0; j < 10; j++) acc[j] = 0.f;
#pragma unroll
    for (int k = 0; k < 64; k++) {
        float a = As[row][k];
#pragma unroll
        for (int j = 0; j < 10; j++) acc[j] += a * Bs[k][cg * 10 + j];
    }
    int gr = row0 + row;
    if (gr < M) {
#pragma unroll
        for (int j = 0; j < 10; j++)
            g_h2[(size_t)gr * D2 + cg * 10 + j] = acc[j];
    }
}

// ---------------- attention coefficients, layer 2 ------------------------------
__global__ void k_att2(const float* __restrict__ s2, const float* __restrict__ d2, int Nn) {
    int n = blockIdx.x * blockDim.x + threadIdx.x;
    if (n >= Nn) return;
    const float* hp = g_h2 + (size_t)n * D2;
    float s = 0.f, d = 0.f;
#pragma unroll
    for (int j = 0; j < D2; j++) {
        float v = hp[j];
        s += v * __ldg(s2 + j);
        d += v * __ldg(d2 + j);
    }
    g_as2[n] = s;
    g_ad2[n] = d;
}

// ---------------- edge pass, layer 2: half-warp per edge, v4 reductions --------
__global__ void k_edge2(const int* __restrict__ ei, int E, int EP) {
    int warp = (blockIdx.x * blockDim.x + threadIdx.x) >> 5;
    int lane = threadIdx.x & 31;
    int half = lane >> 4;
    int lh   = lane & 15;
    int e = warp * 2 + half;
    bool active = (e < EP);
    int src = 0, dst = 0;
    if (active) {
        if (e < E) { src = __ldg(ei + e); dst = __ldg(ei + E + e); }
        else       { src = dst = e - E; }
    }

    float v = g_as2[src] + g_ad2[dst];
    v = (v >= 0.f) ? v : 0.2f * v;
    float ex = __expf(v);
    if (active && lh == 0) atomicAdd(&g_den2[dst], ex);
    if (active && lh < 10) {
        float4 hv = *(const float4*)(g_h2 + (size_t)src * D2 + lh * 4);
        red_v4(g_out2 + (size_t)dst * D2 + lh * 4,
               make_float4(hv.x * ex, hv.y * ex, hv.z * ex, hv.w * ex));
    }
}

// ---------------- final: normalize + bias + log_softmax (warp per node) --------
__global__ void k_lsm(const float* __restrict__ b2, float* __restrict__ out, int Nn) {
    int w = (blockIdx.x * blockDim.x + threadIdx.x) >> 5;
    int lane = threadIdx.x & 31;
    if (w >= Nn) return;
    float inv = 1.f / (g_den2[w] + 1e-16f);
    const float* op = g_out2 + (size_t)w * D2;
    float v0 = op[lane] * inv + __ldg(b2 + lane);
    float v1 = (lane < 8) ? (op[32 + lane] * inv + __ldg(b2 + 32 + lane)) : -3.4e38f;
    float m = fmaxf(v0, v1);
#pragma unroll
    for (int off = 16; off; off >>= 1) m = fmaxf(m, __shfl_xor_sync(0xffffffffu, m, off));
    float s = expf(v0 - m) + ((lane < 8) ? expf(v1 - m) : 0.f);
#pragma unroll
    for (int off = 16; off; off >>= 1) s += __shfl_xor_sync(0xffffffffu, s, off);
    float l = m + logf(s);
    out[(size_t)w * D2 + lane] = v0 - l;
    if (lane < 8) out[(size_t)w * D2 + 32 + lane] = v1 - l;
}

// ---------------- launch --------------------------------------------------------
extern "C" void kernel_launch(void* const* d_in, const int* in_sizes, int n_in,
                              void* d_out, int out_size) {
    const float* x   = (const float*)d_in[0];
    const int*   ei  = (const int*)d_in[1];       // int32 (JAX x64 disabled)
    const float* W1  = (const float*)d_in[2];
    const float* as1 = (const float*)d_in[3];
    const float* ad1 = (const float*)d_in[4];
    const float* b1  = (const float*)d_in[5];
    const float* W2  = (const float*)d_in[6];
    const float* as2 = (const float*)d_in[7];
    const float* ad2 = (const float*)d_in[8];
    const float* b2  = (const float*)d_in[9];

    int Nn = in_sizes[0] / FIN;      // 50000
    int E  = in_sizes[1] / 2;        // 1600000
    int EP = E + Nn;                 // edges + self loops
    int ewarps  = (EP + 1) / 2;      // 2 edges per warp
    int eblocks = (ewarps + 7) / 8;  // 8 warps per block

    k_zero <<<1024, 256>>>(Nn);
    k_gemm1<<<(Nn + 127) / 128, 256>>>(x, W1, Nn);
    k_att1 <<<(Nn * H1N + 255) / 256, 256>>>(as1, ad1, Nn);
    k_edge1<<<eblocks, 256>>>(ei, E, EP);
    k_gemm2<<<(Nn + 63) / 64, 256>>>(W2, b1, Nn);
    k_att2 <<<(Nn + 255) / 256, 256>>>(as2, ad2, Nn);
    k_edge2<<<eblocks, 256>>>(ei, E, EP);
    k_lsm  <<<(Nn + 7) / 8, 256>>>(b2, (float*)d_out, Nn);
}

// round 6
// speedup vs baseline: 1.6967x; 1.0735x over previous
#include <cuda_runtime.h>
#include <cuda_bf16.h>
#include <math.h>

// ---------------- problem constants ----------------
#define NMAX 50048            // N = 50000 nodes (padded)
#define EMAX 1600512
#define FIN  512
#define D1   64               // H1*hid = 8*8
#define H1N  8
#define D2   40               // C (H2=1)

// ---------------- scratch (device globals; no allocation allowed) ----------------
__device__ __align__(16) float g_h1 [NMAX * D1];   // x @ W1
__device__ __align__(16) float g_as1[NMAX * H1N];
__device__ __align__(16) float g_ad1[NMAX * H1N];
__device__ __align__(16) float g_z1 [NMAX * D1];   // relu(softmax-agg + b1): GEMM2 input
__device__ __align__(16) float g_h2 [NMAX * D2];
__device__ __align__(16) float g_as2[NMAX];
__device__ __align__(16) float g_ad2[NMAX];
// CSR-by-dst (built once per launch, shared by both layers)
__device__ int g_cnt[NMAX];
__device__ int g_row[NMAX + 1];
__device__ int g_cur[NMAX];
__device__ int g_srt[EMAX];      // src ids, grouped by dst

__device__ __forceinline__ unsigned tf32_of(float x) {
    unsigned r;
    asm("cvt.rna.tf32.f32 %0, %1;" : "=r"(r) : "f"(x));
    return r;
}
__device__ __forceinline__ float lrelu(float v) { return (v >= 0.f) ? v : 0.2f * v; }

// ---------------- CSR build ------------------------------------------------------
__global__ void k_zero(int Nn) {
    int i = blockIdx.x * blockDim.x + threadIdx.x;
    if (i < Nn) g_cnt[i] = 0;
}
__global__ void k_hist(const int* __restrict__ ei, int E) {
    int i = blockIdx.x * blockDim.x + threadIdx.x;
    if (i < E) atomicAdd(&g_cnt[__ldg(ei + E + i)], 1);
}
__global__ void k_scan(int Nn) {     // single block, 1024 threads
    __shared__ int sh[1024];
    int t = threadIdx.x;
    const int C = (Nn + 1023) >> 10;
    int base = t * C;
    int s = 0;
    for (int i = 0; i < C; i++) {
        int idx = base + i;
        if (idx < Nn) s += g_cnt[idx];
    }
    sh[t] = s;
    __syncthreads();
    for (int off = 1; off < 1024; off <<= 1) {
        int v = (t >= off) ? sh[t - off] : 0;
        __syncthreads();
        sh[t] += v;
        __syncthreads();
    }
    int run = (t == 0) ? 0 : sh[t - 1];
    for (int i = 0; i < C; i++) {
        int idx = base + i;
        if (idx < Nn) {
            g_row[idx] = run;
            g_cur[idx] = run;
            run += g_cnt[idx];
        }
    }
    if (t == 1023) g_row[Nn] = sh[1023];
}
__global__ void k_scatter(const int* __restrict__ ei, int E) {
    int i = blockIdx.x * blockDim.x + threadIdx.x;
    if (i >= E) return;
    int s = __ldg(ei + i), d = __ldg(ei + E + i);
    int p = atomicAdd(&g_cur[d], 1);
    g_srt[p] = s;
}

// ---------------- GEMM1 (tf32 MMA): h1 = x @ W1   (M x 512) @ (512 x 64) -------
__global__ void k_gemm1(const float* __restrict__ A, const float* __restrict__ B, int M) {
    __shared__ __align__(16) float As[128 * 36];
    __shared__ __align__(16) float Bs[64 * 36];
    const int tid  = threadIdx.x;
    const int warp = tid >> 5, lane = tid & 31;
    const int row0 = blockIdx.x * 128;
    const int lr = lane >> 2, lc = lane & 3;

    float acc[8][4];
#pragma unroll
    for (int nt = 0; nt < 8; nt++)
#pragma unroll
        for (int j = 0; j < 4; j++) acc[nt][j] = 0.f;

    for (int k0 = 0; k0 < FIN; k0 += 32) {
#pragma unroll
        for (int i = 0; i < 4; i++) {
            int idx = tid + i * 256;
            int r = idx >> 3, c4 = idx & 7;
            float4 v = make_float4(0.f, 0.f, 0.f, 0.f);
            int gr = row0 + r;
            if (gr < M) v = *(const float4*)(A + (size_t)gr * FIN + k0 + c4 * 4);
            int c = c4 * 4;
            As[r * 36 + ((c + 0) & 7) * 4 + ((c + 0) >> 3)] = __uint_as_float(tf32_of(v.x));
            As[r * 36 + ((c + 1) & 7) * 4 + ((c + 1) >> 3)] = __uint_as_float(tf32_of(v.y));
            As[r * 36 + ((c + 2) & 7) * 4 + ((c + 2) >> 3)] = __uint_as_float(tf32_of(v.z));
            As[r * 36 + ((c + 3) & 7) * 4 + ((c + 3) >> 3)] = __uint_as_float(tf32_of(v.w));
        }
#pragma unroll
        for (int i = 0; i < 2; i++) {
            int idx = tid + i * 256;
            int k = idx >> 4, c4 = idx & 15;
            float4 v = *(const float4*)(B + (size_t)(k0 + k) * D1 + c4 * 4);
            int kk = ((k & 7) << 2) + (k >> 3);
            Bs[(c4 * 4 + 0) * 36 + kk] = __uint_as_float(tf32_of(v.x));
            Bs[(c4 * 4 + 1) * 36 + kk] = __uint_as_float(tf32_of(v.y));
            Bs[(c4 * 4 + 2) * 36 + kk] = __uint_as_float(tf32_of(v.z));
            Bs[(c4 * 4 + 3) * 36 + kk] = __uint_as_float(tf32_of(v.w));
        }
        __syncthreads();

        const float* ab = As + (warp * 16 + lr) * 36;
        float4 a00 = *(const float4*)(ab +        lc * 4);
        float4 a10 = *(const float4*)(ab + 8*36 + lc * 4);
        float4 a01 = *(const float4*)(ab +        (lc + 4) * 4);
        float4 a11 = *(const float4*)(ab + 8*36 + (lc + 4) * 4);
        const unsigned* a00u = (const unsigned*)&a00;
        const unsigned* a10u = (const unsigned*)&a10;
        const unsigned* a01u = (const unsigned*)&a01;
        const unsigned* a11u = (const unsigned*)&a11;

#pragma unroll
        for (int nt = 0; nt < 8; nt++) {
            const float* bb = Bs + (nt * 8 + lr) * 36;
            float4 b0v = *(const float4*)(bb + lc * 4);
            float4 b1v = *(const float4*)(bb + (lc + 4) * 4);
            const unsigned* b0u = (const unsigned*)&b0v;
            const unsigned* b1u = (const unsigned*)&b1v;
#pragma unroll
            for (int ks = 0; ks < 4; ks++) {
                asm volatile(
                    "mma.sync.aligned.m16n8k8.row.col.f32.tf32.tf32.f32 "
                    "{%0,%1,%2,%3}, {%4,%5,%6,%7}, {%8,%9}, {%0,%1,%2,%3};"
                    : "+f"(acc[nt][0]), "+f"(acc[nt][1]), "+f"(acc[nt][2]), "+f"(acc[nt][3])
                    : "r"(a00u[ks]), "r"(a10u[ks]), "r"(a01u[ks]), "r"(a11u[ks]),
                      "r"(b0u[ks]), "r"(b1u[ks]));
            }
        }
        __syncthreads();
    }

    int gr = row0 + warp * 16 + lr;
#pragma unroll
    for (int nt = 0; nt < 8; nt++) {
        int col = nt * 8 + lc * 2;
        if (gr < M)     *(float2*)(g_h1 + (size_t)gr * D1 + col)       = make_float2(acc[nt][0], acc[nt][1]);
        if (gr + 8 < M) *(float2*)(g_h1 + (size_t)(gr + 8) * D1 + col) = make_float2(acc[nt][2], acc[nt][3]);
    }
}

// ---------------- attention coefficients, layer 1 ------------------------------
__global__ void k_att1(const float* __restrict__ asrc, const float* __restrict__ adst, int Nn) {
    int idx = blockIdx.x * blockDim.x + threadIdx.x;
    if (idx >= Nn * H1N) return;
    int n = idx >> 3, h = idx & 7;
    const float* hp = g_h1 + (size_t)n * D1 + h * 8;
    float s = 0.f, d = 0.f;
#pragma unroll
    for (int c = 0; c < 8; c++) {
        float v = hp[c];
        s += v * __ldg(asrc + h * 8 + c);
        d += v * __ldg(adst + h * 8 + c);
    }
    g_as1[idx] = s;
    g_ad1[idx] = d;
}

// ---------------- layer-1 aggregate: warp per dst node --------------------------
// lane owns features {2l, 2l+1}; head = l>>2. Fuses /den + b1 + relu -> g_z1.
__global__ void k_agg1(const float* __restrict__ b1, int Nn) {
    int n = (blockIdx.x * blockDim.x + threadIdx.x) >> 5;
    int lane = threadIdx.x & 31;
    if (n >= Nn) return;
    int h = lane >> 2;
    int f = lane * 2;
    float adh = g_ad1[n * H1N + h];

    // self-loop
    float ex = __expf(lrelu(g_as1[n * H1N + h] + adh));
    float2 hv = *(const float2*)(g_h1 + (size_t)n * D1 + f);
    float a0 = ex * hv.x, a1 = ex * hv.y;
    float den = ((lane & 3) == 0) ? ex : 0.f;

    int j = g_row[n], end = g_row[n + 1];
    // unroll-2 over incoming edges for MLP
    for (; j + 2 <= end; j += 2) {
        int s0 = __ldg(g_srt + j), s1 = __ldg(g_srt + j + 1);
        float e0 = __ldg(g_as1 + s0 * H1N + h) + adh;
        float e1 = __ldg(g_as1 + s1 * H1N + h) + adh;
        float2 v0 = *(const float2*)(g_h1 + (size_t)s0 * D1 + f);
        float2 v1 = *(const float2*)(g_h1 + (size_t)s1 * D1 + f);
        float x0 = __expf(lrelu(e0)), x1 = __expf(lrelu(e1));
        a0 += x0 * v0.x; a1 += x0 * v0.y;
        a0 += x1 * v1.x; a1 += x1 * v1.y;
        if ((lane & 3) == 0) den += x0 + x1;
    }
    if (j < end) {
        int s0 = __ldg(g_srt + j);
        float x0 = __expf(lrelu(__ldg(g_as1 + s0 * H1N + h) + adh));
        float2 v0 = *(const float2*)(g_h1 + (size_t)s0 * D1 + f);
        a0 += x0 * v0.x; a1 += x0 * v0.y;
        if ((lane & 3) == 0) den += x0;
    }

    float dh = __shfl_sync(0xffffffffu, den, h * 4);
    float inv = 1.f / (dh + 1e-16f);
    float z0 = fmaxf(a0 * inv + __ldg(b1 + f),     0.f);
    float z1 = fmaxf(a1 * inv + __ldg(b1 + f + 1), 0.f);
    *(float2*)(g_z1 + (size_t)n * D1 + f) = make_float2(z0, z1);
}

// ---------------- GEMM2: h2 = z1 @ W2  (M x 64) @ (64 x 40) --------------------
__global__ void k_gemm2(const float* __restrict__ W2, int M) {
    __shared__ __align__(16) float As[64][65];
    __shared__ __align__(16) float Bs[64][D2];
    const int tid = threadIdx.x;
    const int row0 = blockIdx.x * 64;

    for (int idx = tid; idx < 64 * D2; idx += 256)
        Bs[idx / D2][idx % D2] = W2[idx];

#pragma unroll
    for (int i = 0; i < 4; i++) {
        int idx = tid + i * 256;
        int r = idx >> 4, c = idx & 15;
        int gr = row0 + r;
        float4 v = make_float4(0.f, 0.f, 0.f, 0.f);
        if (gr < M) v = *(const float4*)(g_z1 + (size_t)gr * D1 + c * 4);
        As[r][c * 4 + 0] = v.x; As[r][c * 4 + 1] = v.y;
        As[r][c * 4 + 2] = v.z; As[r][c * 4 + 3] = v.w;
    }
    __syncthreads();

    int row = tid & 63;
    int cg  = tid >> 6;
    float acc[10];
#pragma unroll
    for (int j = 0; j < 10; j++) acc[j] = 0.f;
#pragma unroll
    for (int k = 0; k < 64; k++) {
        float a = As[row][k];
#pragma unroll
        for (int j = 0; j < 10; j++) acc[j] += a * Bs[k][cg * 10 + j];
    }
    int gr = row0 + row;
    if (gr < M) {
#pragma unroll
        for (int j = 0; j < 10; j++)
            g_h2[(size_t)gr * D2 + cg * 10 + j] = acc[j];
    }
}

// ---------------- attention coefficients, layer 2 ------------------------------
__global__ void k_att2(const float* __restrict__ s2, const float* __restrict__ d2, int Nn) {
    int n = blockIdx.x * blockDim.x + threadIdx.x;
    if (n >= Nn) return;
    const float* hp = g_h2 + (size_t)n * D2;
    float s = 0.f, d = 0.f;
#pragma unroll
    for (int j = 0; j < D2; j++) {
        float v = hp[j];
        s += v * __ldg(s2 + j);
        d += v * __ldg(d2 + j);
    }
    g_as2[n] = s;
    g_ad2[n] = d;
}

// ---------------- layer-2 aggregate + bias + log_softmax: warp per node --------
__global__ void k_agg2(const float* __restrict__ b2, float* __restrict__ out, int Nn) {
    int n = (blockIdx.x * blockDim.x + threadIdx.x) >> 5;
    int lane = threadIdx.x & 31;
    if (n >= Nn) return;
    bool act = (lane < 20);
    int f = lane * 2;
    float adn = g_ad2[n];

    // self-loop
    float ex = __expf(lrelu(g_as2[n] + adn));
    float a0 = 0.f, a1 = 0.f;
    if (act) {
        float2 hv = *(const float2*)(g_h2 + (size_t)n * D2 + f);
        a0 = ex * hv.x; a1 = ex * hv.y;
    }
    float den = ex;

    int j = g_row[n], end = g_row[n + 1];
    for (; j + 2 <= end; j += 2) {
        int s0 = __ldg(g_srt + j), s1 = __ldg(g_srt + j + 1);
        float x0 = __expf(lrelu(__ldg(g_as2 + s0) + adn));
        float x1 = __expf(lrelu(__ldg(g_as2 + s1) + adn));
        if (act) {
            float2 v0 = *(const float2*)(g_h2 + (size_t)s0 * D2 + f);
            float2 v1 = *(const float2*)(g_h2 + (size_t)s1 * D2 + f);
            a0 += x0 * v0.x; a1 += x0 * v0.y;
            a0 += x1 * v1.x; a1 += x1 * v1.y;
        }
        den += x0 + x1;
    }
    if (j < end) {
        int s0 = __ldg(g_srt + j);
        float x0 = __expf(lrelu(__ldg(g_as2 + s0) + adn));
        if (act) {
            float2 v0 = *(const float2*)(g_h2 + (size_t)s0 * D2 + f);
            a0 += x0 * v0.x; a1 += x0 * v0.y;
        }
        den += x0;
    }

    float inv = 1.f / (den + 1e-16f);
    float v0 = -3.4e38f, v1 = -3.4e38f;
    if (act) {
        v0 = a0 * inv + __ldg(b2 + f);
        v1 = a1 * inv + __ldg(b2 + f + 1);
    }
    float m = fmaxf(v0, v1);
#pragma unroll
    for (int off = 16; off; off >>= 1) m = fmaxf(m, __shfl_xor_sync(0xffffffffu, m, off));
    float s = act ? (expf(v0 - m) + expf(v1 - m)) : 0.f;
#pragma unroll
    for (int off = 16; off; off >>= 1) s += __shfl_xor_sync(0xffffffffu, s, off);
    float l = m + logf(s);
    if (act) *(float2*)(out + (size_t)n * D2 + f) = make_float2(v0 - l, v1 - l);
}

// ---------------- launch --------------------------------------------------------
extern "C" void kernel_launch(void* const* d_in, const int* in_sizes, int n_in,
                              void* d_out, int out_size) {
    const float* x   = (const float*)d_in[0];
    const int*   ei  = (const int*)d_in[1];       // int32 (JAX x64 disabled)
    const float* W1  = (const float*)d_in[2];
    const float* as1 = (const float*)d_in[3];
    const float* ad1 = (const float*)d_in[4];
    const float* b1  = (const float*)d_in[5];
    const float* W2  = (const float*)d_in[6];
    const float* as2 = (const float*)d_in[7];
    const float* ad2 = (const float*)d_in[8];
    const float* b2  = (const float*)d_in[9];

    int Nn = in_sizes[0] / FIN;      // 50000
    int E  = in_sizes[1] / 2;        // 1600000
    int nb = (Nn * 32 + 255) / 256;  // warp-per-node grids

    k_zero   <<<(Nn + 255) / 256, 256>>>(Nn);
    k_hist   <<<(E + 255) / 256, 256>>>(ei, E);
    k_scan   <<<1, 1024>>>(Nn);
    k_scatter<<<(E + 255) / 256, 256>>>(ei, E);
    k_gemm1  <<<(Nn + 127) / 128, 256>>>(x, W1, Nn);
    k_att1   <<<(Nn * H1N + 255) / 256, 256>>>(as1, ad1, Nn);
    k_agg1   <<<nb, 256>>>(b1, Nn);
    k_gemm2  <<<(Nn + 63) / 64, 256>>>(W2, Nn);
    k_att2   <<<(Nn + 255) / 256, 256>>>(as2, ad2, Nn);
    k_agg2   <<<nb, 256>>>(b2, (float*)d_out, Nn);
}

// round 7
// speedup vs baseline: 2.1534x; 1.2692x over previous
#include <cuda_runtime.h>
#include <cuda_bf16.h>
#include <math.h>

// ---------------- problem constants ----------------
#define NMAX 50048            // N = 50000 nodes (padded)
#define EMAX 1600512
#define FIN  512
#define D1   64               // H1*hid = 8*8
#define H1N  8
#define D2   40               // C (H2=1)
#define SCB  196              // scan blocks: 196*256 = 50176 >= 50000

// ---------------- scratch (device globals; no allocation allowed) ----------------
__device__ __align__(16) float g_h1 [NMAX * D1];   // x @ W1
__device__ __align__(16) float g_as1[NMAX * H1N];
__device__ __align__(16) float g_ad1[NMAX * H1N];
__device__ __align__(16) float g_z1 [NMAX * D1];   // relu(softmax-agg + b1): GEMM2 input
__device__ __align__(16) float g_h2 [NMAX * D2];
__device__ __align__(16) float g_as2[NMAX];
__device__ __align__(16) float g_ad2[NMAX];
// CSR-by-dst (built once per launch, shared by both layers)
__device__ int g_cnt[NMAX];
__device__ int g_row[NMAX + 1];
__device__ int g_cur[NMAX];
__device__ int g_part[SCB + 1];
__device__ int g_srt[EMAX];      // src ids, grouped by dst

__device__ __forceinline__ unsigned tf32_of(float x) {
    unsigned r;
    asm("cvt.rna.tf32.f32 %0, %1;" : "=r"(r) : "f"(x));
    return r;
}
__device__ __forceinline__ float lrelu(float v) { return (v >= 0.f) ? v : 0.2f * v; }

// ---------------- CSR build ------------------------------------------------------
__global__ void k_zero(int Nn) {
    int i = blockIdx.x * blockDim.x + threadIdx.x;
    if (i < NMAX) g_cnt[i] = 0;
}
__global__ void k_hist(const int* __restrict__ ei, int E) {
    int i = blockIdx.x * blockDim.x + threadIdx.x;
    if (i < E) atomicAdd(&g_cnt[__ldg(ei + E + i)], 1);
}
// phase 1: per-block chunk sums
__global__ void k_scan1() {
    __shared__ int sh[256];
    int t = threadIdx.x, b = blockIdx.x;
    int i = b * 256 + t;
    int v = (i < NMAX) ? g_cnt[i] : 0;
    sh[t] = v;
    __syncthreads();
#pragma unroll
    for (int off = 128; off; off >>= 1) {
        if (t < off) sh[t] += sh[t + off];
        __syncthreads();
    }
    if (t == 0) g_part[b] = sh[0];
}
// phase 2: exclusive scan of SCB partials (single small block)
__global__ void k_scan2() {
    __shared__ int sh[SCB];
    int t = threadIdx.x;
    int v = (t < SCB) ? g_part[t] : 0;
    if (t < SCB) sh[t] = v;
    __syncthreads();
    for (int off = 1; off < SCB; off <<= 1) {
        int u = 0;
        if (t < SCB && t >= off) u = sh[t - off];
        __syncthreads();
        if (t < SCB) sh[t] += u;
        __syncthreads();
    }
    if (t < SCB) g_part[t] = sh[t] - v;   // exclusive
    if (t == SCB - 1) g_part[SCB] = sh[SCB - 1];
}
// phase 3: per-chunk exclusive scan + offset -> g_row, g_cur
__global__ void k_scan3(int Nn) {
    __shared__ int sh[256];
    int t = threadIdx.x, b = blockIdx.x;
    int i = b * 256 + t;
    int v = (i < NMAX) ? g_cnt[i] : 0;
    sh[t] = v;
    __syncthreads();
    for (int off = 1; off < 256; off <<= 1) {
        int u = (t >= off) ? sh[t - off] : 0;
        __syncthreads();
        sh[t] += u;
        __syncthreads();
    }
    int excl = sh[t] - v + g_part[b];
    if (i <= Nn) {                 // Nn entry gets total via cnt[Nn]==0 path
        g_row[i] = excl;
        if (i < Nn) g_cur[i] = excl;
    }
    if (i == Nn) g_row[Nn] = excl; // == total since cnt beyond Nn is 0
}
__global__ void k_scatter(const int* __restrict__ ei, int E) {
    int i = blockIdx.x * blockDim.x + threadIdx.x;
    if (i >= E) return;
    int s = __ldg(ei + i), d = __ldg(ei + E + i);
    int p = atomicAdd(&g_cur[d], 1);
    g_srt[p] = s;
}

// ---------------- GEMM1 (tf32 MMA): h1 = x @ W1   (M x 512) @ (512 x 64) -------
__global__ void k_gemm1(const float* __restrict__ A, const float* __restrict__ B, int M) {
    __shared__ __align__(16) float As[128 * 36];
    __shared__ __align__(16) float Bs[64 * 36];
    const int tid  = threadIdx.x;
    const int warp = tid >> 5, lane = tid & 31;
    const int row0 = blockIdx.x * 128;
    const int lr = lane >> 2, lc = lane & 3;

    float acc[8][4];
#pragma unroll
    for (int nt = 0; nt < 8; nt++)
#pragma unroll
        for (int j = 0; j < 4; j++) acc[nt][j] = 0.f;

    for (int k0 = 0; k0 < FIN; k0 += 32) {
#pragma unroll
        for (int i = 0; i < 4; i++) {
            int idx = tid + i * 256;
            int r = idx >> 3, c4 = idx & 7;
            float4 v = make_float4(0.f, 0.f, 0.f, 0.f);
            int gr = row0 + r;
            if (gr < M) v = *(const float4*)(A + (size_t)gr * FIN + k0 + c4 * 4);
            int c = c4 * 4;
            As[r * 36 + ((c + 0) & 7) * 4 + ((c + 0) >> 3)] = __uint_as_float(tf32_of(v.x));
            As[r * 36 + ((c + 1) & 7) * 4 + ((c + 1) >> 3)] = __uint_as_float(tf32_of(v.y));
            As[r * 36 + ((c + 2) & 7) * 4 + ((c + 2) >> 3)] = __uint_as_float(tf32_of(v.z));
            As[r * 36 + ((c + 3) & 7) * 4 + ((c + 3) >> 3)] = __uint_as_float(tf32_of(v.w));
        }
#pragma unroll
        for (int i = 0; i < 2; i++) {
            int idx = tid + i * 256;
            int k = idx >> 4, c4 = idx & 15;
            float4 v = *(const float4*)(B + (size_t)(k0 + k) * D1 + c4 * 4);
            int kk = ((k & 7) << 2) + (k >> 3);
            Bs[(c4 * 4 + 0) * 36 + kk] = __uint_as_float(tf32_of(v.x));
            Bs[(c4 * 4 + 1) * 36 + kk] = __uint_as_float(tf32_of(v.y));
            Bs[(c4 * 4 + 2) * 36 + kk] = __uint_as_float(tf32_of(v.z));
            Bs[(c4 * 4 + 3) * 36 + kk] = __uint_as_float(tf32_of(v.w));
        }
        __syncthreads();

        const float* ab = As + (warp * 16 + lr) * 36;
        float4 a00 = *(const float4*)(ab +        lc * 4);
        float4 a10 = *(const float4*)(ab + 8*36 + lc * 4);
        float4 a01 = *(const float4*)(ab +        (lc + 4) * 4);
        float4 a11 = *(const float4*)(ab + 8*36 + (lc + 4) * 4);
        const unsigned* a00u = (const unsigned*)&a00;
        const unsigned* a10u = (const unsigned*)&a10;
        const unsigned* a01u = (const unsigned*)&a01;
        const unsigned* a11u = (const unsigned*)&a11;

#pragma unroll
        for (int nt = 0; nt < 8; nt++) {
            const float* bb = Bs + (nt * 8 + lr) * 36;
            float4 b0v = *(const float4*)(bb + lc * 4);
            float4 b1v = *(const float4*)(bb + (lc + 4) * 4);
            const unsigned* b0u = (const unsigned*)&b0v;
            const unsigned* b1u = (const unsigned*)&b1v;
#pragma unroll
            for (int ks = 0; ks < 4; ks++) {
                asm volatile(
                    "mma.sync.aligned.m16n8k8.row.col.f32.tf32.tf32.f32 "
                    "{%0,%1,%2,%3}, {%4,%5,%6,%7}, {%8,%9}, {%0,%1,%2,%3};"
                    : "+f"(acc[nt][0]), "+f"(acc[nt][1]), "+f"(acc[nt][2]), "+f"(acc[nt][3])
                    : "r"(a00u[ks]), "r"(a10u[ks]), "r"(a01u[ks]), "r"(a11u[ks]),
                      "r"(b0u[ks]), "r"(b1u[ks]));
            }
        }
        __syncthreads();
    }

    int gr = row0 + warp * 16 + lr;
#pragma unroll
    for (int nt = 0; nt < 8; nt++) {
        int col = nt * 8 + lc * 2;
        if (gr < M)     *(float2*)(g_h1 + (size_t)gr * D1 + col)       = make_float2(acc[nt][0], acc[nt][1]);
        if (gr + 8 < M) *(float2*)(g_h1 + (size_t)(gr + 8) * D1 + col) = make_float2(acc[nt][2], acc[nt][3]);
    }
}

// ---------------- attention coefficients, layer 1 ------------------------------
__global__ void k_att1(const float* __restrict__ asrc, const float* __restrict__ adst, int Nn) {
    int idx = blockIdx.x * blockDim.x + threadIdx.x;
    if (idx >= Nn * H1N) return;
    int n = idx >> 3, h = idx & 7;
    const float* hp = g_h1 + (size_t)n * D1 + h * 8;
    float s = 0.f, d = 0.f;
#pragma unroll
    for (int c = 0; c < 8; c++) {
        float v = hp[c];
        s += v * __ldg(asrc + h * 8 + c);
        d += v * __ldg(adst + h * 8 + c);
    }
    g_as1[idx] = s;
    g_ad1[idx] = d;
}

// ---------------- layer-1 aggregate: warp per dst node --------------------------
// lane owns features {2l, 2l+1}; head = l>>2. Fuses /den + b1 + relu -> g_z1.
__global__ void k_agg1(const float* __restrict__ b1, int Nn) {
    int n = (blockIdx.x * blockDim.x + threadIdx.x) >> 5;
    int lane = threadIdx.x & 31;
    if (n >= Nn) return;
    int h = lane >> 2;
    int f = lane * 2;
    float adh = g_ad1[n * H1N + h];

    // self-loop
    float ex = __expf(lrelu(g_as1[n * H1N + h] + adh));
    float2 hv = *(const float2*)(g_h1 + (size_t)n * D1 + f);
    float a0 = ex * hv.x, a1 = ex * hv.y;
    float den = ((lane & 3) == 0) ? ex : 0.f;

    int j = g_row[n], end = g_row[n + 1];
    for (; j + 2 <= end; j += 2) {
        int s0 = __ldg(g_srt + j), s1 = __ldg(g_srt + j + 1);
        float e0 = __ldg(g_as1 + s0 * H1N + h) + adh;
        float e1 = __ldg(g_as1 + s1 * H1N + h) + adh;
        float2 v0 = *(const float2*)(g_h1 + (size_t)s0 * D1 + f);
        float2 v1 = *(const float2*)(g_h1 + (size_t)s1 * D1 + f);
        float x0 = __expf(lrelu(e0)), x1 = __expf(lrelu(e1));
        a0 += x0 * v0.x; a1 += x0 * v0.y;
        a0 += x1 * v1.x; a1 += x1 * v1.y;
        if ((lane & 3) == 0) den += x0 + x1;
    }
    if (j < end) {
        int s0 = __ldg(g_srt + j);
        float x0 = __expf(lrelu(__ldg(g_as1 + s0 * H1N + h) + adh));
        float2 v0 = *(const float2*)(g_h1 + (size_t)s0 * D1 + f);
        a0 += x0 * v0.x; a1 += x0 * v0.y;
        if ((lane & 3) == 0) den += x0;
    }

    float dh = __shfl_sync(0xffffffffu, den, h * 4);
    float inv = 1.f / (dh + 1e-16f);
    float z0 = fmaxf(a0 * inv + __ldg(b1 + f),     0.f);
    float z1 = fmaxf(a1 * inv + __ldg(b1 + f + 1), 0.f);
    *(float2*)(g_z1 + (size_t)n * D1 + f) = make_float2(z0, z1);
}

// ---------------- GEMM2: h2 = z1 @ W2  (M x 64) @ (64 x 40) --------------------
__global__ void k_gemm2(const float* __restrict__ W2, int M) {
    __shared__ __align__(16) float As[64][65];
    __shared__ __align__(16) float Bs[64][D2];
    const int tid = threadIdx.x;
    const int row0 = blockIdx.x * 64;

    for (int idx = tid; idx < 64 * D2; idx += 256)
        Bs[idx / D2][idx % D2] = W2[idx];

#pragma unroll
    for (int i = 0; i < 4; i++) {
        int idx = tid + i * 256;
        int r = idx >> 4, c = idx & 15;
        int gr = row0 + r;
        float4 v = make_float4(0.f, 0.f, 0.f, 0.f);
        if (gr < M) v = *(const float4*)(g_z1 + (size_t)gr * D1 + c * 4);
        As[r][c * 4 + 0] = v.x; As[r][c * 4 + 1] = v.y;
        As[r][c * 4 + 2] = v.z; As[r][c * 4 + 3] = v.w;
    }
    __syncthreads();

    int row = tid & 63;
    int cg  = tid >> 6;
    float acc[10];
#pragma unroll
    for (int j = 0; j < 10; j++) acc[j] = 0.f;
#pragma unroll
    for (int k = 0; k < 64; k++) {
        float a = As[row][k];
#pragma unroll
        for (int j = 0; j < 10; j++) acc[j] += a * Bs[k][cg * 10 + j];
    }
    int gr = row0 + row;
    if (gr < M) {
#pragma unroll
        for (int j = 0; j < 10; j++)
            g_h2[(size_t)gr * D2 + cg * 10 + j] = acc[j];
    }
}

// ---------------- attention coefficients, layer 2 ------------------------------
__global__ void k_att2(const float* __restrict__ s2, const float* __restrict__ d2, int Nn) {
    int n = blockIdx.x * blockDim.x + threadIdx.x;
    if (n >= Nn) return;
    const float* hp = g_h2 + (size_t)n * D2;
    float s = 0.f, d = 0.f;
#pragma unroll
    for (int j = 0; j < D2; j++) {
        float v = hp[j];
        s += v * __ldg(s2 + j);
        d += v * __ldg(d2 + j);
    }
    g_as2[n] = s;
    g_ad2[n] = d;
}

// ---------------- layer-2 aggregate + bias + log_softmax: warp per node --------
__global__ void k_agg2(const float* __restrict__ b2, float* __restrict__ out, int Nn) {
    int n = (blockIdx.x * blockDim.x + threadIdx.x) >> 5;
    int lane = threadIdx.x & 31;
    if (n >= Nn) return;
    bool act = (lane < 20);
    int f = lane * 2;
    float adn = g_ad2[n];

    // self-loop
    float ex = __expf(lrelu(g_as2[n] + adn));
    float a0 = 0.f, a1 = 0.f;
    if (act) {
        float2 hv = *(const float2*)(g_h2 + (size_t)n * D2 + f);
        a0 = ex * hv.x; a1 = ex * hv.y;
    }
    float den = ex;

    int j = g_row[n], end = g_row[n + 1];
    for (; j + 2 <= end; j += 2) {
        int s0 = __ldg(g_srt + j), s1 = __ldg(g_srt + j + 1);
        float x0 = __expf(lrelu(__ldg(g_as2 + s0) + adn));
        float x1 = __expf(lrelu(__ldg(g_as2 + s1) + adn));
        if (act) {
            float2 v0 = *(const float2*)(g_h2 + (size_t)s0 * D2 + f);
            float2 v1 = *(const float2*)(g_h2 + (size_t)s1 * D2 + f);
            a0 += x0 * v0.x; a1 += x0 * v0.y;
            a0 += x1 * v1.x; a1 += x1 * v1.y;
        }
        den += x0 + x1;
    }
    if (j < end) {
        int s0 = __ldg(g_srt + j);
        float x0 = __expf(lrelu(__ldg(g_as2 + s0) + adn));
        if (act) {
            float2 v0 = *(const float2*)(g_h2 + (size_t)s0 * D2 + f);
            a0 += x0 * v0.x; a1 += x0 * v0.y;
        }
        den += x0;
    }

    float inv = 1.f / (den + 1e-16f);
    float v0 = -3.4e38f, v1 = -3.4e38f;
    if (act) {
        v0 = a0 * inv + __ldg(b2 + f);
        v1 = a1 * inv + __ldg(b2 + f + 1);
    }
    float m = fmaxf(v0, v1);
#pragma unroll
    for (int off = 16; off; off >>= 1) m = fmaxf(m, __shfl_xor_sync(0xffffffffu, m, off));
    float s = act ? (expf(v0 - m) + expf(v1 - m)) : 0.f;
#pragma unroll
    for (int off = 16; off; off >>= 1) s += __shfl_xor_sync(0xffffffffu, s, off);
    float l = m + logf(s);
    if (act) *(float2*)(out + (size_t)n * D2 + f) = make_float2(v0 - l, v1 - l);
}

// ---------------- launch --------------------------------------------------------
extern "C" void kernel_launch(void* const* d_in, const int* in_sizes, int n_in,
                              void* d_out, int out_size) {
    const float* x   = (const float*)d_in[0];
    const int*   ei  = (const int*)d_in[1];       // int32 (JAX x64 disabled)
    const float* W1  = (const float*)d_in[2];
    const float* as1 = (const float*)d_in[3];
    const float* ad1 = (const float*)d_in[4];
    const float* b1  = (const float*)d_in[5];
    const float* W2  = (const float*)d_in[6];
    const float* as2 = (const float*)d_in[7];
    const float* ad2 = (const float*)d_in[8];
    const float* b2  = (const float*)d_in[9];

    int Nn = in_sizes[0] / FIN;      // 50000
    int E  = in_sizes[1] / 2;        // 1600000
    int nb = (Nn * 32 + 255) / 256;  // warp-per-node grids

    k_zero   <<<(NMAX + 255) / 256, 256>>>(Nn);
    k_hist   <<<(E + 255) / 256, 256>>>(ei, E);
    k_scan1  <<<SCB, 256>>>();
    k_scan2  <<<1, 256>>>();
    k_scan3  <<<SCB, 256>>>(Nn);
    k_scatter<<<(E + 255) / 256, 256>>>(ei, E);
    k_gemm1  <<<(Nn + 127) / 128, 256>>>(x, W1, Nn);
    k_att1   <<<(Nn * H1N + 255) / 256, 256>>>(as1, ad1, Nn);
    k_agg1   <<<nb, 256>>>(b1, Nn);
    k_gemm2  <<<(Nn + 63) / 64, 256>>>(W2, Nn);
    k_att2   <<<(Nn + 255) / 256, 256>>>(as2, ad2, Nn);
    k_agg2   <<<nb, 256>>>(b2, (float*)d_out, Nn);
}